// round 17
// baseline (speedup 1.0000x reference)
#include <cuda_runtime.h>
#include <math.h>

// ---------------- problem constants ----------------
#define BB 16
#define TT 8
#define HW 196
#define HID 32
#define IND 16
#define KBIG 6272       // HID*HW
#define K0 588          // CIN*HW
#define K0PAD 640
#define NBU 3136        // IND*HW
#define NTD 9408        // (IND+HID)*HW
#define KS_TD 24
#define KS_BU 49
#define KS_B0 5
#define GSEG (16 * 64 * 196)
#define CSEG (16 * 32 * 196)

// ---------------- device scratch (no allocs allowed) ----------------
__device__ float g_h[3 * 2 * BB * HID * HW];   // hidden, double buffered
__device__ float g_xT[TT * K0PAD * BB];        // transposed+padded input slices
__device__ float g_pH0[KBIG * BB];
__device__ float g_pH1[KBIG * BB];
__device__ float g_pH2[KBIG * BB];
__device__ float g_bu[BB * NBU];
__device__ float g_bu1e[BB * NBU];             // epilogue shared bu1
__device__ float g_bu0all[TT * BB * NBU];
__device__ float g_td[BB * NTD];
__device__ float g_part[KS_TD * BB * NTD];
__device__ float g_partB[KS_BU * BB * NBU];
__device__ float g_partBe[KS_BU * BB * NBU];
__device__ float g_partB0[TT * KS_B0 * BB * NBU];
__device__ float g_gp[8 * GSEG];               // gate partials (8 ic-slices)
__device__ float g_cp[8 * CSEG];
__device__ float g_gp0[8 * GSEG];
__device__ float g_cp0[8 * CSEG];
__device__ float g_fc1o[BB * 100];
__device__ float g_tdw0T[(size_t)KBIG * NTD];
__device__ float g_tdw1T[(size_t)KBIG * NTD];
__device__ float g_buw1T[(size_t)KBIG * NBU];
__device__ float g_buw2T[(size_t)KBIG * NBU];
__device__ float g_buw0T[(size_t)K0PAD * NBU];
// fused-reduction counters (zero-init; each use resets itself)
__device__ int g_gcnt[2][32];                  // [gemm sub-problem][bx]
__device__ int g_ccnt[2][16][8];               // [cand sub-problem][b][grp]

// ---------------- f32x2 helpers ----------------
__device__ __forceinline__ unsigned long long pack2(float v) {
    unsigned long long r;
    asm("mov.b64 %0, {%1, %1};" : "=l"(r) : "f"(v));
    return r;
}
__device__ __forceinline__ void fma2(unsigned long long& d, unsigned long long a,
                                     unsigned long long b) {
    asm("fma.rn.f32x2 %0, %1, %2, %0;" : "+l"(d) : "l"(a), "l"(b));
}
__device__ __forceinline__ float sigm(float a) { return 1.f / (1.f + expf(-a)); }

// ---------------- float4 transposes ----------------
__global__ void trans2_k(const float* __restrict__ Wa, float* __restrict__ WTa,
                         const float* __restrict__ Wb, float* __restrict__ WTb,
                         int Nout) {
    __shared__ float t[32][33];
    const float* W  = blockIdx.z ? Wb  : Wa;
    float*       WT = blockIdx.z ? WTb : WTa;
    const int kb = blockIdx.x * 32, nb = blockIdx.y * 32;
    const int tid = threadIdx.x;                   // 256
    {
        int n = tid >> 3, q = tid & 7;
        float4 v = *(const float4*)(W + (size_t)(nb + n) * KBIG + kb + q * 4);
        t[q * 4 + 0][n] = v.x; t[q * 4 + 1][n] = v.y;
        t[q * 4 + 2][n] = v.z; t[q * 4 + 3][n] = v.w;
    }
    __syncthreads();
    {
        int k = tid >> 3, q = tid & 7;
        float4 v = make_float4(t[k][q * 4], t[k][q * 4 + 1],
                               t[k][q * 4 + 2], t[k][q * 4 + 3]);
        *(float4*)(WT + (size_t)(kb + k) * Nout + nb + q * 4) = v;
    }
}

__global__ void trans_pad_k(const float* __restrict__ W, float* __restrict__ WT,
                            int Nout) {
    __shared__ float t[32][33];
    const int kb = blockIdx.x * 32, nb = blockIdx.y * 32;
    const int tid = threadIdx.x;
    {
        int n = tid >> 3, q = tid & 7;
        float4 v = make_float4(0.f, 0.f, 0.f, 0.f);
        if ((kb >> 2) + q < 147)
            v = *(const float4*)(W + (size_t)(nb + n) * K0 + kb + q * 4);
        t[q * 4 + 0][n] = v.x; t[q * 4 + 1][n] = v.y;
        t[q * 4 + 2][n] = v.z; t[q * 4 + 3][n] = v.w;
    }
    __syncthreads();
    {
        int k = tid >> 3, q = tid & 7;
        float4 v = make_float4(t[k][q * 4], t[k][q * 4 + 1],
                               t[k][q * 4 + 2], t[k][q * 4 + 3]);
        *(float4*)(WT + (size_t)(kb + k) * Nout + nb + q * 4) = v;
    }
}

// ================= gemmT core =================
__device__ __forceinline__ void gemmT_core(
    float* sa, const float* __restrict__ act, const float* __restrict__ WT,
    float* __restrict__ part, int Nout, int KS, int ks, int bx, int Kpad)
{
    const int tid = threadIdx.x;
    const int n0raw = bx * 512 + tid * 2;
    const bool act_n = n0raw < Nout;
    const int n0 = act_n ? n0raw : (Nout - 2);
    const int slabs = Kpad >> 7;
    const int s0 = slabs * ks / KS, s1 = slabs * (ks + 1) / KS;
    const int ns = s1 - s0;
    const int kn = ns * 128;

    {
        const float4* src = (const float4*)act + (size_t)s0 * 512;
        for (int f = tid; f < ns * 512; f += 256) {
            float4 v = src[f];
            *(float4*)(&sa[(f >> 2) * 16 + (f & 3) * 4]) = v;
        }
    }

    unsigned long long acc[2][8];
#pragma unroll
    for (int n = 0; n < 2; n++)
#pragma unroll
        for (int p = 0; p < 8; p++) acc[n][p] = 0ull;

    const float* wp = WT + (size_t)(s0 * 128) * Nout + n0;
    float2 wb[2][8];
#pragma unroll
    for (int u = 0; u < 8; u++)
        wb[0][u] = *(const float2*)(wp + (size_t)u * Nout);

    __syncthreads();

    for (int k0 = 0; k0 < kn; k0 += 8) {
        const int cur = (k0 >> 3) & 1;
        const float* wpn = wp + (size_t)8 * Nout;
        if (k0 + 8 < kn) {
#pragma unroll
            for (int u = 0; u < 8; u++)
                wb[cur ^ 1][u] = *(const float2*)(wpn + (size_t)u * Nout);
        }
#pragma unroll
        for (int u = 0; u < 8; u++) {
            const ulonglong2* ap = (const ulonglong2*)(sa + (k0 + u) * 16);
            ulonglong2 u0 = ap[0], u1 = ap[1], u2 = ap[2], u3 = ap[3];
            unsigned long long av[8] = {u0.x, u0.y, u1.x, u1.y,
                                        u2.x, u2.y, u3.x, u3.y};
            unsigned long long w0 = pack2(wb[cur][u].x);
            unsigned long long w1 = pack2(wb[cur][u].y);
#pragma unroll
            for (int p = 0; p < 8; p++) fma2(acc[0][p], w0, av[p]);
#pragma unroll
            for (int p = 0; p < 8; p++) fma2(acc[1][p], w1, av[p]);
        }
        wp = wpn;
    }
    if (act_n) {
        float* op = part + (size_t)ks * 16 * Nout + n0;
#pragma unroll
        for (int b = 0; b < 16; b++) {
            unsigned long long v0 = acc[0][b >> 1], v1 = acc[1][b >> 1];
            float f0 = (b & 1) ? __uint_as_float((unsigned)(v0 >> 32))
                               : __uint_as_float((unsigned)v0);
            float f1 = (b & 1) ? __uint_as_float((unsigned)(v1 >> 32))
                               : __uint_as_float((unsigned)v1);
            op[(size_t)b * Nout + 0] = f0;
            op[(size_t)b * Nout + 1] = f1;
        }
    }
}

// last-block fused reduce: deterministic (bias first, ks ascending)
__device__ __forceinline__ void gemm_finish(
    int* s_last, const float* __restrict__ part, const float* __restrict__ bias,
    float* __restrict__ out, int Nout, int KS, int bx, int* cnt)
{
    __syncthreads();                       // all partial stores issued
    if (threadIdx.x == 0) {
        __threadfence();
        *s_last = (atomicAdd(cnt, 1) == KS - 1);
    }
    __syncthreads();
    if (!*s_last) return;
    for (int i = threadIdx.x; i < 16 * 512; i += 256) {
        int b = i >> 9, nl = i & 511, n = bx * 512 + nl;
        if (n < Nout) {
            float a = bias[n];
            for (int ks = 0; ks < KS; ks++)
                a += part[((size_t)ks * 16 + b) * Nout + n];
            out[(size_t)b * Nout + n] = a;
        }
    }
    if (threadIdx.x == 0) *cnt = 0;        // reset for next launch/replay
}

__global__ void __launch_bounds__(256) gemmTR_k(
    const float* __restrict__ act, const float* __restrict__ WT,
    float* __restrict__ part, const float* __restrict__ bias,
    float* __restrict__ out, int Nout, int KS, int Kpad)
{
    __shared__ float sa[3 * 128 * 16];
    __shared__ int s_last;
    gemmT_core(sa, act, WT, part, Nout, KS, blockIdx.y, blockIdx.x, Kpad);
    gemm_finish(&s_last, part, bias, out, Nout, KS, blockIdx.x,
                &g_gcnt[0][blockIdx.x]);
}

__global__ void __launch_bounds__(256) gemmTR2_k(
    const float* __restrict__ actA, const float* __restrict__ WTA,
    float* __restrict__ partA, const float* __restrict__ bA,
    float* __restrict__ oA, int NoutA, int KSA, int KpadA,
    const float* __restrict__ actB, const float* __restrict__ WTB,
    float* __restrict__ partB, const float* __restrict__ bB,
    float* __restrict__ oB, int NoutB, int KSB, int KpadB)
{
    __shared__ float sa[3 * 128 * 16];
    __shared__ int s_last;
    const int y = blockIdx.y, bx = blockIdx.x;
    if (y < KSA) {
        if (bx * 512 >= NoutA) return;
        gemmT_core(sa, actA, WTA, partA, NoutA, KSA, y, bx, KpadA);
        gemm_finish(&s_last, partA, bA, oA, NoutA, KSA, bx, &g_gcnt[0][bx]);
    } else {
        if (bx * 512 >= NoutB) return;
        gemmT_core(sa, actB, WTB, partB, NoutB, KSB, y - KSA, bx, KpadB);
        gemm_finish(&s_last, partB, bB, oB, NoutB, KSB, bx, &g_gcnt[1][bx]);
    }
}

__global__ void __launch_bounds__(256) gemmB0all_k(
    const float* __restrict__ xT, const float* __restrict__ WT,
    float* __restrict__ partAll)
{
    __shared__ float sa[3 * 128 * 16];
    const int y = blockIdx.y;
    const int t = y / KS_B0, ks = y - t * KS_B0;
    gemmT_core(sa, xT + (size_t)t * K0PAD * 16, WT,
               partAll + (size_t)t * KS_B0 * 16 * NBU,
               NBU, KS_B0, ks, blockIdx.x, K0PAD);
}

__device__ __forceinline__ void red_one(const float* __restrict__ p,
                                        const float* __restrict__ bias,
                                        float* __restrict__ o, int N, int KS,
                                        int i) {
    int n = i % N;
    float a = bias[n];
    for (int ks = 0; ks < KS; ks++) a += p[(size_t)ks * 16 * N + i];
    o[i] = a;
}
__global__ void reduceB0all_k(const float* __restrict__ partAll,
                              const float* __restrict__ bias,
                              float* __restrict__ outAll) {
    int i = blockIdx.x * 256 + threadIdx.x;
    if (i >= TT * 16 * NBU) return;
    int t = i / (16 * NBU), j = i - t * 16 * NBU;
    red_one(partAll + (size_t)t * KS_B0 * 16 * NBU, bias,
            outAll + (size_t)t * 16 * NBU, NBU, KS_B0, j);
}

// ================= conv bodies: 2 pixels/thread, 6 ics/block (oct 0..7) ====
__device__ __forceinline__ void gate_body(
    float* sc, float* sw,
    const float* __restrict__ bu, const float* __restrict__ h,
    const float* __restrict__ td, const float* __restrict__ Wg,
    float* __restrict__ gp, int has_td, int b, int grp, int oct)
{
    const int ic0 = oct * 6;
    const int tid = threadIdx.x;                    // 128
    for (int i = tid; i < 6 * 256; i += 128) sc[i] = 0.f;
    for (int i = tid; i < 6 * 36; i += 128) {
        int lic = i / 36, rem = i - lic * 36, q = rem >> 2, o = rem & 3;
        sw[i] = Wg[(grp * 4 + o) * 432 + (ic0 + lic) * 9 + q];
    }
    __syncthreads();
    for (int i = tid; i < 6 * 196; i += 128) {
        int lic = i / 196, p = i - lic * 196, y = p / 14, x = p - y * 14;
        int ic = ic0 + lic;
        float v = (ic < IND) ? bu[((size_t)b * IND + ic) * 196 + p]
                             : h[((size_t)b * HID + (ic - IND)) * 196 + p];
        if (has_td) v += td[((size_t)b * 48 + ic) * 196 + p];
        sc[lic * 256 + (y + 1) * 16 + (x + 1)] = v;
    }
    __syncthreads();
    if (tid < 98) {
        const int y = tid / 7, xp = tid - y * 7, x0 = 2 * xp;
        float4 aA = make_float4(0.f, 0.f, 0.f, 0.f);
        float4 aB = make_float4(0.f, 0.f, 0.f, 0.f);
        const float* cbase = sc + y * 16 + x0;
        for (int lic = 0; lic < 6; ++lic) {
            const float* cb = cbase + lic * 256;
            float v[3][4];
#pragma unroll
            for (int dy = 0; dy < 3; dy++)
#pragma unroll
                for (int dx = 0; dx < 4; dx++) v[dy][dx] = cb[dy * 16 + dx];
            const float4* wq = (const float4*)(sw + lic * 36);
#pragma unroll
            for (int dy = 0; dy < 3; dy++)
#pragma unroll
                for (int dx = 0; dx < 3; dx++) {
                    float4 w = wq[dy * 3 + dx];
                    float vA = v[dy][dx], vB = v[dy][dx + 1];
                    aA.x += w.x * vA; aA.y += w.y * vA;
                    aA.z += w.z * vA; aA.w += w.w * vA;
                    aB.x += w.x * vB; aB.y += w.y * vB;
                    aB.z += w.z * vB; aB.w += w.w * vB;
                }
        }
        int pA = y * 14 + x0;
        float* o = gp + (size_t)oct * GSEG + ((size_t)b * 64 + grp * 4) * 196 + pA;
        o[0]   = aA.x; o[196] = aA.y; o[392] = aA.z; o[588] = aA.w;
        o[1]   = aB.x; o[197] = aB.y; o[393] = aB.z; o[589] = aB.w;
    }
}

__device__ __forceinline__ void cand_body(
    float* sc, float* sw,
    const float* __restrict__ bu, const float* __restrict__ h,
    const float* __restrict__ gp, const float* __restrict__ bg,
    const float* __restrict__ Wc, float* __restrict__ cp,
    int b, int grp, int oct)
{
    const int ic0 = oct * 6;
    const int tid = threadIdx.x;
    for (int i = tid; i < 6 * 256; i += 128) sc[i] = 0.f;
    for (int i = tid; i < 6 * 36; i += 128) {
        int lic = i / 36, rem = i - lic * 36, q = rem >> 2, o = rem & 3;
        sw[i] = Wc[(grp * 4 + o) * 432 + (ic0 + lic) * 9 + q];
    }
    __syncthreads();
    for (int i = tid; i < 6 * 196; i += 128) {
        int lic = i / 196, p = i - lic * 196, y = p / 14, x = p - y * 14;
        int ic = ic0 + lic;
        float v;
        if (ic < IND) {
            v = bu[((size_t)b * IND + ic) * 196 + p];
        } else {
            int c = ic - IND;
            size_t gi = ((size_t)b * 64 + c) * 196 + p;
            float s = bg[c];
#pragma unroll
            for (int q = 0; q < 8; q++) s += gp[gi + (size_t)q * GSEG];
            v = sigm(s) * h[((size_t)b * HID + c) * 196 + p];
        }
        sc[lic * 256 + (y + 1) * 16 + (x + 1)] = v;
    }
    __syncthreads();
    if (tid < 98) {
        const int y = tid / 7, xp = tid - y * 7, x0 = 2 * xp;
        float4 aA = make_float4(0.f, 0.f, 0.f, 0.f);
        float4 aB = make_float4(0.f, 0.f, 0.f, 0.f);
        const float* cbase = sc + y * 16 + x0;
        for (int lic = 0; lic < 6; ++lic) {
            const float* cb = cbase + lic * 256;
            float v[3][4];
#pragma unroll
            for (int dy = 0; dy < 3; dy++)
#pragma unroll
                for (int dx = 0; dx < 4; dx++) v[dy][dx] = cb[dy * 16 + dx];
            const float4* wq = (const float4*)(sw + lic * 36);
#pragma unroll
            for (int dy = 0; dy < 3; dy++)
#pragma unroll
                for (int dx = 0; dx < 3; dx++) {
                    float4 w = wq[dy * 3 + dx];
                    float vA = v[dy][dx], vB = v[dy][dx + 1];
                    aA.x += w.x * vA; aA.y += w.y * vA;
                    aA.z += w.z * vA; aA.w += w.w * vA;
                    aB.x += w.x * vB; aB.y += w.y * vB;
                    aB.z += w.z * vB; aB.w += w.w * vB;
                }
        }
        int pA = y * 14 + x0;
        float* o = cp + (size_t)oct * CSEG + ((size_t)b * 32 + grp * 4) * 196 + pA;
        o[0]   = aA.x; o[196] = aA.y; o[392] = aA.z; o[588] = aA.w;
        o[1]   = aB.x; o[197] = aB.y; o[393] = aB.z; o[589] = aB.w;
    }
}

// last-block fused GRU-update + maxpool + transpose (counts 8 oct blocks)
__device__ __forceinline__ void cand_finish(
    int* s_last, float* sp,
    const float* __restrict__ cp, const float* __restrict__ bc,
    const float* __restrict__ gp, const float* __restrict__ bg,
    const float* __restrict__ h, float* __restrict__ hnew,
    float* __restrict__ poolT, int b, int grp, int* cnt)
{
    __syncthreads();
    if (threadIdx.x == 0) {
        __threadfence();
        *s_last = (atomicAdd(cnt, 1) == 7);
    }
    __syncthreads();
    if (!*s_last) return;
    const int tid = threadIdx.x;
    for (int g = 0; g < 4; g++) {
        const int oc = grp * 4 + g;
        for (int i = tid; i < 256; i += 128) sp[i] = -3.4e38f;
        __syncthreads();
        for (int p = tid; p < 196; p += 128) {
            int y = p / 14, x = p - y * 14;
            size_t i = ((size_t)b * 32 + oc) * 196 + p;
            float a = bc[oc];
#pragma unroll
            for (int q = 0; q < 8; q++) a += cp[i + (size_t)q * CSEG];
            size_t gi = ((size_t)b * 64 + 32 + oc) * 196 + p;
            float zs = bg[32 + oc];
#pragma unroll
            for (int q = 0; q < 8; q++) zs += gp[gi + (size_t)q * GSEG];
            float z = sigm(zs);
            float hn = (1.f - z) * h[i] + z * tanhf(a);
            hnew[i] = hn;
            sp[(y + 1) * 16 + (x + 1)] = hn;
        }
        __syncthreads();
        for (int p = tid; p < 196; p += 128) {
            int y = p / 14, x = p - y * 14;
            const float* c = sp + y * 16 + x;
            float m = c[0];
            m = fmaxf(m, c[1]);  m = fmaxf(m, c[2]);
            m = fmaxf(m, c[16]); m = fmaxf(m, c[17]); m = fmaxf(m, c[18]);
            m = fmaxf(m, c[32]); m = fmaxf(m, c[33]); m = fmaxf(m, c[34]);
            poolT[((size_t)oc * 196 + p) * 16 + b] = m;
        }
        __syncthreads();
    }
    if (tid == 0) *cnt = 0;
}

// single-node conv kernels (128 threads)
__global__ void __launch_bounds__(128) gate_part_k(
    const float* __restrict__ bu, const float* __restrict__ h,
    const float* __restrict__ td, const float* __restrict__ Wg,
    float* __restrict__ gp, int has_td)
{
    __shared__ float sc[6 * 256];
    __shared__ float sw[6 * 36];
    gate_body(sc, sw, bu, h, td, Wg, gp, has_td,
              blockIdx.x, blockIdx.y, blockIdx.z);
}
__global__ void __launch_bounds__(128) cand_part_k(
    const float* __restrict__ bu, const float* __restrict__ h,
    const float* __restrict__ gp, const float* __restrict__ bg,
    const float* __restrict__ Wc, float* __restrict__ cp,
    const float* __restrict__ bc, float* __restrict__ hnew,
    float* __restrict__ poolT)
{
    __shared__ float sc[6 * 256];
    __shared__ float sw[6 * 36];
    __shared__ int s_last;
    cand_body(sc, sw, bu, h, gp, bg, Wc, cp, blockIdx.x, blockIdx.y, blockIdx.z);
    cand_finish(&s_last, sc, cp, bc, gp, bg, h, hnew, poolT,
                blockIdx.x, blockIdx.y, &g_ccnt[0][blockIdx.x][blockIdx.y]);
}

// merged two-node conv kernels (PAIR: A=node2 no-td, B=node0 with td)
__global__ void __launch_bounds__(128) gate_part2_k(
    const float* __restrict__ buA, const float* __restrict__ hA,
    const float* __restrict__ WgA, float* __restrict__ gpA,
    const float* __restrict__ buB, const float* __restrict__ hB,
    const float* __restrict__ tdB, const float* __restrict__ WgB,
    float* __restrict__ gpB)
{
    __shared__ float sc[6 * 256];
    __shared__ float sw[6 * 36];
    const int z = blockIdx.z;
    if (z < 8)
        gate_body(sc, sw, buA, hA, tdB, WgA, gpA, 0, blockIdx.x, blockIdx.y, z);
    else
        gate_body(sc, sw, buB, hB, tdB, WgB, gpB, 1, blockIdx.x, blockIdx.y, z - 8);
}
__global__ void __launch_bounds__(128) cand_part2_k(
    const float* __restrict__ buA, const float* __restrict__ hA,
    const float* __restrict__ gpA, const float* __restrict__ bgA,
    const float* __restrict__ WcA, float* __restrict__ cpA,
    const float* __restrict__ bcA, float* __restrict__ hnA,
    float* __restrict__ poolA,
    const float* __restrict__ buB, const float* __restrict__ hB,
    const float* __restrict__ gpB, const float* __restrict__ bgB,
    const float* __restrict__ WcB, float* __restrict__ cpB,
    const float* __restrict__ bcB, float* __restrict__ hnB,
    float* __restrict__ poolB)
{
    __shared__ float sc[6 * 256];
    __shared__ float sw[6 * 36];
    __shared__ int s_last;
    const int z = blockIdx.z, b = blockIdx.x, grp = blockIdx.y;
    if (z < 8) {
        cand_body(sc, sw, buA, hA, gpA, bgA, WcA, cpA, b, grp, z);
        cand_finish(&s_last, sc, cpA, bcA, gpA, bgA, hA, hnA, poolA,
                    b, grp, &g_ccnt[0][b][grp]);
    } else {
        cand_body(sc, sw, buB, hB, gpB, bgB, WcB, cpB, b, grp, z - 8);
        cand_finish(&s_last, sc, cpB, bcB, gpB, bgB, hB, hnB, poolB,
                    b, grp, &g_ccnt[1][b][grp]);
    }
}

// ---------------- misc ----------------
__global__ void xT_k(const float* __restrict__ x, float* __restrict__ xT) {
    int idx = blockIdx.x * 256 + threadIdx.x;
    if (idx >= TT * K0PAD * BB) return;
    int b = idx & 15;
    int r = idx >> 4;
    int k = r % K0PAD, t = r / K0PAD;
    float v = 0.f;
    if (k < K0) v = x[((size_t)b * TT + t) * K0 + k];
    xT[idx] = v;
}

__global__ void zero_k(float* p, int n) {
    int i = blockIdx.x * 256 + threadIdx.x;
    if (i < n) p[i] = 0.f;
}

// ---------------- fc tail ----------------
__global__ void __launch_bounds__(256) fc1_k(const float* __restrict__ h2,
                                             const float* __restrict__ w,
                                             const float* __restrict__ bias,
                                             float* __restrict__ out1) {
    __shared__ float red[256];
    int j = blockIdx.x, tid = threadIdx.x;
    float acc[16];
#pragma unroll
    for (int b = 0; b < 16; b++) acc[b] = 0.f;
    for (int k = tid; k < KBIG; k += 256) {
        float wv = w[(size_t)j * KBIG + k];
#pragma unroll
        for (int b = 0; b < 16; b++)
            acc[b] += wv * fmaxf(h2[(size_t)b * KBIG + k], 0.f);
    }
    for (int b = 0; b < 16; b++) {
        red[tid] = acc[b];
        __syncthreads();
        for (int sft = 128; sft; sft >>= 1) {
            if (tid < sft) red[tid] += red[tid + sft];
            __syncthreads();
        }
        if (tid == 0) out1[b * 100 + j] = fmaxf(red[0] + bias[j], 0.f);
        __syncthreads();
    }
}

__global__ void fc2_k(const float* __restrict__ p, const float* __restrict__ w,
                      const float* __restrict__ bias, float* __restrict__ out) {
    int t = threadIdx.x;
    if (t < 160) {
        int b = t / 10, j = t - b * 10;
        float a = bias[j];
        for (int k = 0; k < 100; k++) a += p[b * 100 + k] * w[j * 100 + k];
        out[b * 10 + j] = a;
    }
}

// ---------------- host orchestration ----------------
extern "C" void kernel_launch(void* const* d_in, const int* in_sizes, int n_in,
                              void* d_out, int out_size) {
    const float* x     = (const float*)d_in[0];
    const float* Wg    = (const float*)d_in[1];
    const float* bg    = (const float*)d_in[2];
    const float* Wc    = (const float*)d_in[3];
    const float* bc    = (const float*)d_in[4];
    const float* bu_w0 = (const float*)d_in[5];
    const float* bu_b0 = (const float*)d_in[6];
    const float* bu_w1 = (const float*)d_in[7];
    const float* bu_b1 = (const float*)d_in[8];
    const float* bu_w2 = (const float*)d_in[9];
    const float* bu_b2 = (const float*)d_in[10];
    const float* td_w0 = (const float*)d_in[11];
    const float* td_b0 = (const float*)d_in[12];
    const float* td_w1 = (const float*)d_in[13];
    const float* td_b1 = (const float*)d_in[14];
    const float* fc1_w = (const float*)d_in[15];
    const float* fc1_b = (const float*)d_in[16];
    const float* fc2_w = (const float*)d_in[17];
    const float* fc2_b = (const float*)d_in[18];
    float* out = (float*)d_out;

    float *hbuf, *xT, *pH0, *pH1, *pH2, *bu, *bu1e, *bu0all, *td;
    float *part, *partB, *partBe, *partB0, *gp, *cp, *gp0, *cp0, *fc1o;
    float *tdw0T, *tdw1T, *buw1T, *buw2T, *buw0T;
    cudaGetSymbolAddress((void**)&hbuf,   g_h);
    cudaGetSymbolAddress((void**)&xT,     g_xT);
    cudaGetSymbolAddress((void**)&pH0,    g_pH0);
    cudaGetSymbolAddress((void**)&pH1,    g_pH1);
    cudaGetSymbolAddress((void**)&pH2,    g_pH2);
    cudaGetSymbolAddress((void**)&bu,     g_bu);
    cudaGetSymbolAddress((void**)&bu1e,   g_bu1e);
    cudaGetSymbolAddress((void**)&bu0all, g_bu0all);
    cudaGetSymbolAddress((void**)&td,     g_td);
    cudaGetSymbolAddress((void**)&part,   g_part);
    cudaGetSymbolAddress((void**)&partB,  g_partB);
    cudaGetSymbolAddress((void**)&partBe, g_partBe);
    cudaGetSymbolAddress((void**)&partB0, g_partB0);
    cudaGetSymbolAddress((void**)&gp,     g_gp);
    cudaGetSymbolAddress((void**)&cp,     g_cp);
    cudaGetSymbolAddress((void**)&gp0,    g_gp0);
    cudaGetSymbolAddress((void**)&cp0,    g_cp0);
    cudaGetSymbolAddress((void**)&fc1o,   g_fc1o);
    cudaGetSymbolAddress((void**)&tdw0T,  g_tdw0T);
    cudaGetSymbolAddress((void**)&tdw1T,  g_tdw1T);
    cudaGetSymbolAddress((void**)&buw1T,  g_buw1T);
    cudaGetSymbolAddress((void**)&buw2T,  g_buw2T);
    cudaGetSymbolAddress((void**)&buw0T,  g_buw0T);

    const int hTot = 3 * 2 * BB * HID * HW;
    zero_k<<<(hTot + 255) / 256, 256>>>(hbuf, hTot);
    xT_k<<<(TT * K0PAD * BB + 255) / 256, 256>>>(x, xT);

    const int tdGx = (NTD + 511) / 512, buGx = (NBU + 511) / 512;
    {
        trans2_k<<<dim3(KBIG / 32, NTD / 32, 2), 256>>>(td_w0, tdw0T,
                                                        td_w1, tdw1T, NTD);
        trans2_k<<<dim3(KBIG / 32, NBU / 32, 2), 256>>>(bu_w1, buw1T,
                                                        bu_w2, buw2T, NBU);
        trans_pad_k<<<dim3(K0PAD / 32, NBU / 32), 256>>>(bu_w0, buw0T, NBU);
    }
    gemmB0all_k<<<dim3(buGx, TT * KS_B0), 256>>>(xT, buw0T, partB0);
    reduceB0all_k<<<(TT * 16 * NBU + 255) / 256, 256>>>(partB0, bu_b0, bu0all);

    int cur[3] = {0, 0, 0};
    const size_t HSZ = (size_t)BB * HID * HW;
    const size_t B0SZ = (size_t)16 * NBU;
    const float* WgN[3] = {Wg, Wg + 27648, Wg + 2 * 27648};
    const float* bgN[3] = {bg, bg + 64, bg + 128};
    const float* WcN[3] = {Wc, Wc + 13824, Wc + 2 * 13824};
    const float* bcN[3] = {bc, bc + 32, bc + 64};

    dim3 gateGrid(16, 16, 8), candGrid(16, 8, 8);
    dim3 gate2Grid(16, 16, 16), cand2Grid(16, 8, 16);
#define HPTR(n, p) (hbuf + ((size_t)(n) * 2 + (p)) * HSZ)

#define NODE0_NOTD(tt)                                                         \
    do {                                                                       \
        const float* b0 = bu0all + (size_t)(tt) * B0SZ;                        \
        gate_part_k<<<gateGrid, 128>>>(b0, HPTR(0, cur[0]), td, WgN[0],        \
                                       gp0, 0);                                \
        cand_part_k<<<candGrid, 128>>>(b0, HPTR(0, cur[0]), gp0, bgN[0],       \
                                       WcN[0], cp0, bcN[0],                    \
                                       HPTR(0, 1 - cur[0]), pH0);              \
        cur[0] ^= 1;                                                           \
    } while (0)

#define NODE1(tt)                                                              \
    do {                                                                       \
        int hastd = ((tt) >= 2);                                               \
        if (hastd) {                                                           \
            gemmTR2_k<<<dim3(tdGx, KS_BU + KS_TD), 256>>>(                     \
                pH0, buw1T, partB, bu_b1, bu, NBU, KS_BU, KBIG,                \
                pH2, tdw1T, part, td_b1, td, NTD, KS_TD, KBIG);                \
        } else {                                                               \
            gemmTR_k<<<dim3(buGx, KS_BU), 256>>>(pH0, buw1T, partB, bu_b1,     \
                                                 bu, NBU, KS_BU, KBIG);        \
        }                                                                      \
        gate_part_k<<<gateGrid, 128>>>(bu, HPTR(1, cur[1]), td, WgN[1],        \
                                       gp, hastd);                             \
        cand_part_k<<<candGrid, 128>>>(bu, HPTR(1, cur[1]), gp, bgN[1],        \
                                       WcN[1], cp, bcN[1],                     \
                                       HPTR(1, 1 - cur[1]), pH1);              \
        cur[1] ^= 1;                                                           \
    } while (0)

#define NODE2_CONV()                                                           \
    do {                                                                       \
        gate_part_k<<<gateGrid, 128>>>(bu, HPTR(2, cur[2]), td, WgN[2],        \
                                       gp, 0);                                 \
        cand_part_k<<<candGrid, 128>>>(bu, HPTR(2, cur[2]), gp, bgN[2],        \
                                       WcN[2], cp, bcN[2],                     \
                                       HPTR(2, 1 - cur[2]), pH2);              \
        cur[2] ^= 1;                                                           \
    } while (0)

#define NODE1_EPI_CONV()                                                       \
    do {                                                                       \
        gate_part_k<<<gateGrid, 128>>>(bu1e, HPTR(1, cur[1]), td, WgN[1],      \
                                       gp, 1);                                 \
        cand_part_k<<<candGrid, 128>>>(bu1e, HPTR(1, cur[1]), gp, bgN[1],      \
                                       WcN[1], cp, bcN[1],                     \
                                       HPTR(1, 1 - cur[1]), pH1);              \
        cur[1] ^= 1;                                                           \
    } while (0)

    // ---- prologue: node0(0), node0(1), node1(1) ----
    NODE0_NOTD(0);
    NODE0_NOTD(1);
    NODE1(1);

    // ---- main loop: PAIR{node2(t), node0(t+1)} ; node1(t+1)  for t=1..6 ----
    for (int t = 1; t <= 6; t++) {
        gemmTR2_k<<<dim3(tdGx, KS_BU + KS_TD), 256>>>(
            pH1, buw2T, partB, bu_b2, bu, NBU, KS_BU, KBIG,   // node2 bu
            pH1, tdw0T, part, td_b0, td, NTD, KS_TD, KBIG);   // node0 td
        const float* b0 = bu0all + (size_t)(t + 1) * B0SZ;
        gate_part2_k<<<gate2Grid, 128>>>(bu, HPTR(2, cur[2]), WgN[2], gp,
                                         b0, HPTR(0, cur[0]), td, WgN[0], gp0);
        cand_part2_k<<<cand2Grid, 128>>>(
            bu, HPTR(2, cur[2]), gp, bgN[2], WcN[2], cp, bcN[2],
            HPTR(2, 1 - cur[2]), pH2,
            b0, HPTR(0, cur[0]), gp0, bgN[0], WcN[0], cp0, bcN[0],
            HPTR(0, 1 - cur[0]), pH0);
        cur[2] ^= 1;
        cur[0] ^= 1;
        NODE1(t + 1);
    }

    // ---- epilogue ----
    // E1: node2(7) bu + shared bu1e (h0 frozen after t=7) in one launch
    gemmTR2_k<<<dim3(buGx, KS_BU + KS_BU), 256>>>(
        pH1, buw2T, partB, bu_b2, bu, NBU, KS_BU, KBIG,
        pH0, buw1T, partBe, bu_b1, bu1e, NBU, KS_BU, KBIG);
    NODE2_CONV();                                     // node2(7) -> pH2
    // E2: node1(8): td only
    gemmTR_k<<<dim3(tdGx, KS_TD), 256>>>(pH2, tdw1T, part, td_b1, td,
                                         NTD, KS_TD, KBIG);
    NODE1_EPI_CONV();                                 // node1(8) -> pH1
    // E3: node2(8)
    gemmTR_k<<<dim3(buGx, KS_BU), 256>>>(pH1, buw2T, partB, bu_b2, bu,
                                         NBU, KS_BU, KBIG);
    NODE2_CONV();                                     // node2(8) -> pH2
    // E4: node1(9): td only (bu1e reused)
    gemmTR_k<<<dim3(tdGx, KS_TD), 256>>>(pH2, tdw1T, part, td_b1, td,
                                         NTD, KS_TD, KBIG);
    NODE1_EPI_CONV();                                 // node1(9) -> pH1
    // E5: node2(9)
    gemmTR_k<<<dim3(buGx, KS_BU), 256>>>(pH1, buw2T, partB, bu_b2, bu,
                                         NBU, KS_BU, KBIG);
    NODE2_CONV();

    fc1_k<<<100, 256>>>(HPTR(2, cur[2]), fc1_w, fc1_b, fc1o);
    fc2_k<<<1, 192>>>(fc1o, fc2_w, fc2_b, out);
#undef NODE0_NOTD
#undef NODE1
#undef NODE2_CONV
#undef NODE1_EPI_CONV
#undef HPTR
}